// round 14
// baseline (speedup 1.0000x reference)
#include <cuda_runtime.h>

#define NB 4
#define NG 8
#define HH 32
#define WW 32
#define KS 7
#define PD 3
#define HP 38
#define NPP 1444      // HP*HP
#define NM 392
#define MSK 424       // mod32=8: K-staging STS conflict-free; mult of 4
#define QSTR 36
#define NPIX 1024

#define SM_KS  0
#define SM_AGT (32*MSK)            // 13568 ; Agt[ij*64 + g*8 + g'] (3136)
#define SM_QS  (SM_AGT + 3136)     // 16704 ; [32 c][QSTR]
#define SM_MB  (SM_QS + 32*QSTR)   // 17856  [8w][32r]
#define SM_RI  (SM_MB + 256)       // 18112
#define ATTN_SMEM ((SM_RI + 32)*4) // 72576 B -> 3 CTA/SM

// qconv smem
#define QC_WS 0                    // [128 o][33]
#define QC_XS (128*33)             // [32 k][64 p]
#define QC_OS (QC_XS + 32*64)      // [64 p][132]
#define CONV_SMEM ((QC_OS + 64*132)*4)   // 58880 B
// kvconv smem: all 8 groups per CTA, 16 pixels
#define KV_WS 0                    // [8 g][32 o][36]
#define KV_XS (8*32*36)            // 9216 ; [8 g][16 p][36]
#define KV_OS (KV_XS + 8*16*36)    // 13824 ; [16 p][260]
#define KV_SMEM ((KV_OS + 16*260)*4)     // 71936 B

__device__ float g_q[NB*NPIX*1024];   // [b][p][g*128 + hh*32 + c]  (q * log2e)
__device__ float g_k[NB*NPP*256];     // [b][sp][c*8+g]
__device__ float g_v[NB*NPP*256];

typedef unsigned long long u64;
__device__ __forceinline__ u64 pk2(float a, float b) {
    u64 r; asm("mov.b64 %0, {%1,%2};" : "=l"(r) : "f"(a), "f"(b)); return r;
}
__device__ __forceinline__ void up2(u64 v, float& a, float& b) {
    asm("mov.b64 {%0,%1}, %2;" : "=f"(a), "=f"(b) : "l"(v));
}
#define FMA2(d,a,b) asm("fma.rn.f32x2 %0, %1, %2, %0;" : "+l"(d) : "l"(a), "l"(b))
__device__ __forceinline__ float ex2(float x) {
    float r; asm("ex2.approx.f32 %0, %1;" : "=f"(r) : "f"(x)); return r;
}

// ================= q conv: per (b,g) GEMM 128o x 64p, K=32 =================
__global__ void __launch_bounds__(256) qconv_kernel(const float* __restrict__ x,
                                                    const float* __restrict__ wq,
                                                    const float* __restrict__ bq) {
    extern __shared__ float sm[];
    float* Ws = sm + QC_WS;
    float* Xs = sm + QC_XS;
    float* Os = sm + QC_OS;
    int pt = blockIdx.x, g = blockIdx.y, b = blockIdx.z;
    int t = threadIdx.x;
    #pragma unroll
    for (int u = 0; u < 16; u++) {
        int e = t + 256*u;
        Ws[(e >> 5)*33 + (e & 31)] = wq[g*4096 + e];
    }
    #pragma unroll
    for (int u = 0; u < 8; u++) {
        int e = t + 256*u;
        int k = e >> 6, p = e & 63;
        Xs[e] = x[((b*NG + g)*32 + k)*1024 + pt*64 + p];
    }
    __syncthreads();

    int to = t >> 4, tp = t & 15;
    int o0 = to*8, p0 = tp*4;
    u64 a[8][2];
    #pragma unroll
    for (int i = 0; i < 8; i++) {
        float bi = bq[g*128 + o0 + i];
        a[i][0] = pk2(bi, bi); a[i][1] = a[i][0];
    }
    #pragma unroll 4
    for (int k = 0; k < 32; k++) {
        ulonglong2 xv = *(const ulonglong2*)(Xs + k*64 + p0);
        #pragma unroll
        for (int i = 0; i < 8; i++) {
            float w = Ws[(o0 + i)*33 + k];
            u64 w2 = pk2(w, w);
            FMA2(a[i][0], w2, xv.x);
            FMA2(a[i][1], w2, xv.y);
        }
    }
    const float L2E = 1.4426950408889634f;
    #pragma unroll
    for (int i = 0; i < 8; i++)
        #pragma unroll
        for (int j = 0; j < 2; j++) {
            float lo, hi; up2(a[i][j], lo, hi);
            Os[(p0 + 2*j    )*132 + o0 + i] = lo * L2E;
            Os[(p0 + 2*j + 1)*132 + o0 + i] = hi * L2E;
        }
    __syncthreads();
    #pragma unroll
    for (int u = 0; u < 8; u++) {
        int e = t + 256*u;
        int p = e >> 5, o4 = e & 31;
        float4 v = *(const float4*)(Os + p*132 + o4*4);
        *(float4*)(g_q + (long)(b*1024 + pt*64 + p)*1024 + g*128 + o4*4) = v;
    }
}

// ====== kv conv: all 8 groups, 16 padded px/CTA, coalesced output ======
__global__ void __launch_bounds__(256) kvconv_kernel(const float* __restrict__ x,
                                                     const float* __restrict__ wk,
                                                     const float* __restrict__ bk,
                                                     const float* __restrict__ wv,
                                                     const float* __restrict__ bv) {
    extern __shared__ float sm[];
    float* Ws = sm + KV_WS;   // [g*1152 + o*36 + k]
    float* Xs = sm + KV_XS;   // [g*576 + p*36 + k]
    float* Os = sm + KV_OS;   // [p*260 + c8]
    __shared__ float bs[256];
    int pt = blockIdx.x, kvsel = blockIdx.y, b = blockIdx.z;
    int t = threadIdx.x;
    const float* w  = kvsel ? wv : wk;
    const float* bb = kvsel ? bv : bk;
    float* gout = kvsel ? g_v : g_k;

    #pragma unroll
    for (int u = 0; u < 32; u++) {
        int e = t + 256*u;              // g*1024 + o*32 + k
        int g = e >> 10, o = (e >> 5) & 31, k = e & 31;
        Ws[g*1152 + o*36 + k] = w[e];
    }
    bs[t] = bb[t];
    #pragma unroll
    for (int u = 0; u < 16; u++) {
        int e = t + 256*u;              // g*512 + k*16 + p
        int g = e >> 9, k = (e >> 4) & 31, p = e & 15;
        int sp = pt*16 + p;
        float v = 0.f;
        if (sp < NPP) {
            int sy = sp / HP, sx = sp - sy*HP;
            int iy = sy - PD, ix = sx - PD;
            if (iy >= 0 && iy < HH && ix >= 0 && ix < WW)
                v = x[((b*NG + g)*32 + k)*1024 + iy*32 + ix];
        }
        Xs[g*576 + p*36 + k] = v;
    }
    __syncthreads();

    // thread: p = t&15, oo = t>>4 (o-pair 2oo, 2oo+1); acc over all 8 g
    {
        int p = t & 15, oo = t >> 4;
        u64 acc[8];
        #pragma unroll
        for (int g = 0; g < 8; g++)
            acc[g] = pk2(bs[g*32 + 2*oo], bs[g*32 + 2*oo + 1]);
        #pragma unroll
        for (int g = 0; g < 8; g++) {
            const float* xr = Xs + g*576 + p*36;
            const float* w0 = Ws + g*1152 + (2*oo)*36;
            const float* w1 = w0 + 36;
            #pragma unroll
            for (int k4 = 0; k4 < 8; k4++) {
                float4 xv = *(const float4*)(xr + k4*4);
                float4 wa = *(const float4*)(w0 + k4*4);
                float4 wb = *(const float4*)(w1 + k4*4);
                FMA2(acc[g], pk2(xv.x, xv.x), pk2(wa.x, wb.x));
                FMA2(acc[g], pk2(xv.y, xv.y), pk2(wa.y, wb.y));
                FMA2(acc[g], pk2(xv.z, xv.z), pk2(wa.z, wb.z));
                FMA2(acc[g], pk2(xv.w, xv.w), pk2(wa.w, wb.w));
            }
        }
        #pragma unroll
        for (int g = 0; g < 8; g++) {
            float lo, hi; up2(acc[g], lo, hi);
            Os[p*260 + (2*oo)*8 + g]     = lo;   // [sp][c*8+g], c = o
            Os[p*260 + (2*oo + 1)*8 + g] = hi;
        }
    }
    __syncthreads();

    // coalesced float4 writeout
    #pragma unroll
    for (int u = 0; u < 4; u++) {
        int e = t + 256*u;              // p'*64 + c4
        int pp = e >> 6, c4 = e & 63;
        int sp = pt*16 + pp;
        if (sp < NPP) {
            float4 v = *(const float4*)(Os + pp*260 + c4*4);
            *(float4*)(gout + (long)(b*NPP + sp)*256 + c4*4) = v;
        }
    }
}

// ================= attention =================
// One S-GEMM pass: 8 rows x 4 cols per lane
__device__ __forceinline__ void sgemm_pass(float* Ks, const float* qs,
                                           int r0, int cb, int lcb,
                                           bool valid, bool active, float* rsum) {
    u64 acc[8][2];
    #pragma unroll
    for (int i = 0; i < 8; i++) { acc[i][0] = 0ull; acc[i][1] = 0ull; }
    #pragma unroll 4
    for (int cc = 0; cc < 32; cc++) {
        ulonglong2 k = *(const ulonglong2*)(Ks + cc*MSK + lcb);
        float4 qa = *(const float4*)(qs + cc*QSTR + r0);
        float4 qb = *(const float4*)(qs + cc*QSTR + r0 + 4);
        float qv[8] = {qa.x, qa.y, qa.z, qa.w, qb.x, qb.y, qb.z, qb.w};
        #pragma unroll
        for (int i = 0; i < 8; i++) {
            u64 q2 = pk2(qv[i], qv[i]);
            FMA2(acc[i][0], q2, k.x);
            FMA2(acc[i][1], q2, k.y);
        }
    }
    #pragma unroll
    for (int i = 0; i < 8; i++) {
        float l0, h0, l1, h1;
        up2(acc[i][0], l0, h0); up2(acc[i][1], l1, h1);
        float e0 = ex2(l0), e1 = ex2(h0), e2 = ex2(l1), e3 = ex2(h1);
        if (valid) rsum[i] += e0 + e1 + e2 + e3;
        if (active) {
            u64 s0 = valid ? pk2(e0, e1) : 0ull;
            u64 s1 = valid ? pk2(e2, e3) : 0ull;
            *(ulonglong2*)(Ks + (r0 + i)*MSK + cb) = make_ulonglong2(s0, s1);
        }
    }
}

// 8 warps x 52 cols each (416 total); pass0: 8 chunks, pass1: 5 chunks
__device__ __forceinline__ void sgemm_warp(float* Ks, const float* qs, float* mb,
                                           int w, int tx) {
    int r0 = (tx >> 3) * 8;
    int lane8 = tx & 7;
    int c0 = w*52 + lane8*4;
    int c1 = c0 + 32;
    bool a1 = (lane8 < 5);
    int lc1 = a1 ? c1 : w*52;
    float rsum[8];
    #pragma unroll
    for (int i = 0; i < 8; i++) rsum[i] = 0.f;
    sgemm_pass(Ks, qs, r0, c0, c0, c0 < NM, true, rsum);
    // FIX: inactive lanes must be fully invalid (no rsum), else they exp()
    // stale/overwritten data and double-count neighbor warps' columns.
    sgemm_pass(Ks, qs, r0, c1, lc1, a1 && (c1 < NM), a1, rsum);
    #pragma unroll
    for (int i = 0; i < 8; i++) {
        float s = rsum[i];
        s += __shfl_xor_sync(0xffffffffu, s, 1);
        s += __shfl_xor_sync(0xffffffffu, s, 2);
        s += __shfl_xor_sync(0xffffffffu, s, 4);
        if (lane8 == 0) mb[w*32 + r0 + i] = s;
    }
}

__global__ void __launch_bounds__(256, 3) attn_kernel(const float* __restrict__ rel_h,
                                                      const float* __restrict__ rel_w,
                                                      const float* __restrict__ gv,
                                                      float* __restrict__ out) {
    extern __shared__ float sm[];
    float* Ks   = sm + SM_KS;    // [32 c][MSK] -> E in place
    float* Agt  = sm + SM_AGT;   // [ij][g][g'] 49x8x8
    float* qs   = sm + SM_QS;    // [c][QSTR]
    float* mb   = sm + SM_MB;    // [8 w][32 r]
    float* rinv = sm + SM_RI;
    float* Rs   = Ks;            // O-GEMM partials reuse Ks

    int bp = blockIdx.x;
    int b = bp >> 10, p = bp & 1023;
    int px = p >> 5, py = p & 31;
    int t = threadIdx.x;
    int tx = t & 31, ty = t >> 5;

    // stage q: qs[c*QSTR + hh*8 + g]
    {
        float4 qv = ((const float4*)(g_q + (long)bp*1024))[t];
        int s = t*4;
        int g = s >> 7, hh = (s >> 5) & 3, c0 = s & 31;
        qs[(c0+0)*QSTR + hh*8 + g] = qv.x;
        qs[(c0+1)*QSTR + hh*8 + g] = qv.y;
        qs[(c0+2)*QSTR + hh*8 + g] = qv.z;
        qs[(c0+3)*QSTR + hh*8 + g] = qv.w;
    }

    // stage K(+rel) [c][m]; STS conflict-free (MSK%32==8)
    {
        int c = t >> 3, gq = t & 7;
        float rh[KS];
        #pragma unroll
        for (int u = 0; u < KS; u++)
            rh[u] = (c < 16) ? rel_h[c*56 + gq*7 + u] : rel_w[(c - 16)*56 + gq*7 + u];
        const float* kbase = g_k + ((long)(b*HP + px)*HP + py)*256 + t;
        for (int i = 0; i < KS; i++) {
            #pragma unroll
            for (int j = 0; j < KS; j++) {
                int m = gq*49 + i*7 + j;
                int off = (i*HP + j)*256;
                float rel = (c < 16) ? rh[i] : rh[j];
                Ks[c*MSK + m] = kbase[off] + rel;
            }
        }
    }
    __syncthreads();

    // S = q^T K with fused exp + row sums; all 8 warps, 52 cols each
    sgemm_warp(Ks, qs, mb, ty, tx);
    __syncthreads();

    if (t < 32) {
        float s = 0.f;
        #pragma unroll
        for (int w = 0; w < 8; w++) s += mb[w*32 + t];
        rinv[t] = 1.f / s;
    }
    __syncthreads();

    // collapse heads into Agt[ij*64 + g*8 + g'] (reads only m < 392)
    for (int idx = t; idx < 3136; idx += 256) {
        int ij = idx >> 6;
        int rem = idx & 63;
        int g = rem >> 3, gp = rem & 7;
        int m = gp*49 + ij;
        float s = Ks[g*MSK + m]        * rinv[g]
                + Ks[(8+g)*MSK + m]    * rinv[8+g]
                + Ks[(16+g)*MSK + m]   * rinv[16+g]
                + Ks[(24+g)*MSK + m]   * rinv[24+g];
        Agt[idx] = s;
    }
    __syncthreads();

    // O-GEMM: V straight from gmem (coalesced, consumed once)
    {
        u64 og[8];
        #pragma unroll
        for (int g = 0; g < 8; g++) og[g] = 0ull;
        int c = tx, w = ty;
        const float* vb = gv + ((long)(b*HP + px)*HP + py)*256 + c*8;
        #pragma unroll
        for (int k = 0; k < 7; k++) {
            int ij = k*8 + w;
            if (ij < 49) {
                int i = ij / 7, j = ij - i*7;
                const float4* vp = (const float4*)(vb + (i*HP + j)*256);
                float4 va = vp[0], vbq = vp[1];
                u64 v0 = pk2(va.x, va.y), v1 = pk2(va.z, va.w);
                u64 v2 = pk2(vbq.x, vbq.y), v3 = pk2(vbq.z, vbq.w);
                const float* ab = Agt + ij*64;
                #pragma unroll
                for (int g = 0; g < 8; g++) {
                    ulonglong2 a0 = *(const ulonglong2*)(ab + g*8);
                    ulonglong2 a1 = *(const ulonglong2*)(ab + g*8 + 4);
                    FMA2(og[g], a0.x, v0);
                    FMA2(og[g], a0.y, v1);
                    FMA2(og[g], a1.x, v2);
                    FMA2(og[g], a1.y, v3);
                }
            }
        }
        __syncthreads();   // Agt/E reads done before Rs overwrites Ks
        #pragma unroll
        for (int g = 0; g < 8; g++) {
            float lo, hi; up2(og[g], lo, hi);
            Rs[w*264 + g*33 + c] = lo + hi;
        }
    }
    __syncthreads();

    // final reduce over 8 warps + scrambled store: out[b, g*32+px, py, c]
    {
        int c = tx, g = ty;
        float s = 0.f;
        #pragma unroll
        for (int w = 0; w < 8; w++) s += Rs[w*264 + g*33 + c];
        out[b*262144 + (g*32 + px)*1024 + py*32 + c] = s;
    }
}

// ---------------- launch ----------------
extern "C" void kernel_launch(void* const* d_in, const int* in_sizes, int n_in,
                              void* d_out, int out_size) {
    const float* x   = (const float*)d_in[0];
    const float* wq  = (const float*)d_in[1];
    const float* bq  = (const float*)d_in[2];
    const float* wk  = (const float*)d_in[3];
    const float* bk  = (const float*)d_in[4];
    const float* wv  = (const float*)d_in[5];
    const float* bv  = (const float*)d_in[6];
    const float* rlh = (const float*)d_in[7];
    const float* rlw = (const float*)d_in[8];
    float* out = (float*)d_out;

    cudaFuncSetAttribute(qconv_kernel, cudaFuncAttributeMaxDynamicSharedMemorySize, CONV_SMEM);
    cudaFuncSetAttribute(kvconv_kernel, cudaFuncAttributeMaxDynamicSharedMemorySize, KV_SMEM);
    cudaFuncSetAttribute(attn_kernel, cudaFuncAttributeMaxDynamicSharedMemorySize, ATTN_SMEM);

    qconv_kernel<<<dim3(16, 8, 4), 256, CONV_SMEM>>>(x, wq, bq);
    kvconv_kernel<<<dim3(91, 2, 4), 256, KV_SMEM>>>(x, wk, bk, wv, bv);

    float* gv_ptr = nullptr;
    cudaGetSymbolAddress((void**)&gv_ptr, g_v);
    attn_kernel<<<NB*NPIX, 256, ATTN_SMEM>>>(rlh, rlw, gv_ptr, out);
}

// round 15
// speedup vs baseline: 1.1089x; 1.1089x over previous
#include <cuda_runtime.h>

#define NB 4
#define NG 8
#define HH 32
#define WW 32
#define KS 7
#define PD 3
#define HP 38
#define NPP 1444      // HP*HP
#define NM 392
#define VPAD 416      // padded S cols (stored zeros; collapse reads only m<392)
#define MSK 424       // mod32=8: K-staging STS conflict-free; mult of 4
#define NPIX 1024

#define SM_KS  0
#define SM_AGT (32*MSK)            // 13568 ; Agt[ij*64 + g*8 + g'] (3136)
#define SM_QS  (SM_AGT + 3136)     // 16704 ; [32 c][32 r]
#define SM_MB  (SM_QS + 1024)      // 17728  [8w][32r]
#define SM_RI  (SM_MB + 256)       // 17984
#define ATTN_SMEM ((SM_RI + 32)*4) // 72064 B -> 3 CTA/SM

// qconv smem
#define QC_WS 0                    // [128 o][33]
#define QC_XS (128*33)             // [32 k][64 p]
#define QC_OS (QC_XS + 32*64)      // [64 p][132]
#define CONV_SMEM ((QC_OS + 64*132)*4)   // 58880 B
// kvconv smem: all 8 groups per CTA, 16 pixels
#define KV_WS 0                    // [8 g][32 o][36]
#define KV_XS (8*32*36)            // 9216 ; [8 g][16 p][36]
#define KV_OS (KV_XS + 8*16*36)    // 13824 ; [16 p][260]
#define KV_SMEM ((KV_OS + 16*260)*4)     // 71936 B

__device__ float g_q[NB*NPIX*1024];   // [b][p][g*128 + hh*32 + c]  (q * log2e)
__device__ float g_k[NB*NPP*256];     // [b][sp][c*8+g]
__device__ float g_v[NB*NPP*256];

typedef unsigned long long u64;
__device__ __forceinline__ u64 pk2(float a, float b) {
    u64 r; asm("mov.b64 %0, {%1,%2};" : "=l"(r) : "f"(a), "f"(b)); return r;
}
__device__ __forceinline__ void up2(u64 v, float& a, float& b) {
    asm("mov.b64 {%0,%1}, %2;" : "=f"(a), "=f"(b) : "l"(v));
}
#define FMA2(d,a,b) asm("fma.rn.f32x2 %0, %1, %2, %0;" : "+l"(d) : "l"(a), "l"(b))
__device__ __forceinline__ float ex2(float x) {
    float r; asm("ex2.approx.f32 %0, %1;" : "=f"(r) : "f"(x)); return r;
}

// ================= q conv: per (b,g) GEMM 128o x 64p, K=32 =================
__global__ void __launch_bounds__(256) qconv_kernel(const float* __restrict__ x,
                                                    const float* __restrict__ wq,
                                                    const float* __restrict__ bq) {
    extern __shared__ float sm[];
    float* Ws = sm + QC_WS;
    float* Xs = sm + QC_XS;
    float* Os = sm + QC_OS;
    int pt = blockIdx.x, g = blockIdx.y, b = blockIdx.z;
    int t = threadIdx.x;
    #pragma unroll
    for (int u = 0; u < 16; u++) {
        int e = t + 256*u;
        Ws[(e >> 5)*33 + (e & 31)] = wq[g*4096 + e];
    }
    #pragma unroll
    for (int u = 0; u < 8; u++) {
        int e = t + 256*u;
        int k = e >> 6, p = e & 63;
        Xs[e] = x[((b*NG + g)*32 + k)*1024 + pt*64 + p];
    }
    __syncthreads();

    int to = t >> 4, tp = t & 15;
    int o0 = to*8, p0 = tp*4;
    u64 a[8][2];
    #pragma unroll
    for (int i = 0; i < 8; i++) {
        float bi = bq[g*128 + o0 + i];
        a[i][0] = pk2(bi, bi); a[i][1] = a[i][0];
    }
    #pragma unroll 4
    for (int k = 0; k < 32; k++) {
        ulonglong2 xv = *(const ulonglong2*)(Xs + k*64 + p0);
        #pragma unroll
        for (int i = 0; i < 8; i++) {
            float w = Ws[(o0 + i)*33 + k];
            u64 w2 = pk2(w, w);
            FMA2(a[i][0], w2, xv.x);
            FMA2(a[i][1], w2, xv.y);
        }
    }
    const float L2E = 1.4426950408889634f;
    #pragma unroll
    for (int i = 0; i < 8; i++)
        #pragma unroll
        for (int j = 0; j < 2; j++) {
            float lo, hi; up2(a[i][j], lo, hi);
            Os[(p0 + 2*j    )*132 + o0 + i] = lo * L2E;
            Os[(p0 + 2*j + 1)*132 + o0 + i] = hi * L2E;
        }
    __syncthreads();
    #pragma unroll
    for (int u = 0; u < 8; u++) {
        int e = t + 256*u;
        int p = e >> 5, o4 = e & 31;
        float4 v = *(const float4*)(Os + p*132 + o4*4);
        *(float4*)(g_q + (long)(b*1024 + pt*64 + p)*1024 + g*128 + o4*4) = v;
    }
}

// ====== kv conv: all 8 groups, 16 padded px/CTA, coalesced output ======
__global__ void __launch_bounds__(256) kvconv_kernel(const float* __restrict__ x,
                                                     const float* __restrict__ wk,
                                                     const float* __restrict__ bk,
                                                     const float* __restrict__ wv,
                                                     const float* __restrict__ bv) {
    extern __shared__ float sm[];
    float* Ws = sm + KV_WS;   // [g*1152 + o*36 + k]
    float* Xs = sm + KV_XS;   // [g*576 + p*36 + k]
    float* Os = sm + KV_OS;   // [p*260 + c8]
    __shared__ float bs[256];
    int pt = blockIdx.x, kvsel = blockIdx.y, b = blockIdx.z;
    int t = threadIdx.x;
    const float* w  = kvsel ? wv : wk;
    const float* bb = kvsel ? bv : bk;
    float* gout = kvsel ? g_v : g_k;

    #pragma unroll
    for (int u = 0; u < 32; u++) {
        int e = t + 256*u;              // g*1024 + o*32 + k
        int g = e >> 10, o = (e >> 5) & 31, k = e & 31;
        Ws[g*1152 + o*36 + k] = w[e];
    }
    bs[t] = bb[t];
    #pragma unroll
    for (int u = 0; u < 16; u++) {
        int e = t + 256*u;              // g*512 + k*16 + p
        int g = e >> 9, k = (e >> 4) & 31, p = e & 15;
        int sp = pt*16 + p;
        float v = 0.f;
        if (sp < NPP) {
            int sy = sp / HP, sx = sp - sy*HP;
            int iy = sy - PD, ix = sx - PD;
            if (iy >= 0 && iy < HH && ix >= 0 && ix < WW)
                v = x[((b*NG + g)*32 + k)*1024 + iy*32 + ix];
        }
        Xs[g*576 + p*36 + k] = v;
    }
    __syncthreads();

    {
        int p = t & 15, oo = t >> 4;
        u64 acc[8];
        #pragma unroll
        for (int g = 0; g < 8; g++)
            acc[g] = pk2(bs[g*32 + 2*oo], bs[g*32 + 2*oo + 1]);
        #pragma unroll
        for (int g = 0; g < 8; g++) {
            const float* xr = Xs + g*576 + p*36;
            const float* w0 = Ws + g*1152 + (2*oo)*36;
            const float* w1 = w0 + 36;
            #pragma unroll
            for (int k4 = 0; k4 < 8; k4++) {
                float4 xv = *(const float4*)(xr + k4*4);
                float4 wa = *(const float4*)(w0 + k4*4);
                float4 wb = *(const float4*)(w1 + k4*4);
                FMA2(acc[g], pk2(xv.x, xv.x), pk2(wa.x, wb.x));
                FMA2(acc[g], pk2(xv.y, xv.y), pk2(wa.y, wb.y));
                FMA2(acc[g], pk2(xv.z, xv.z), pk2(wa.z, wb.z));
                FMA2(acc[g], pk2(xv.w, xv.w), pk2(wa.w, wb.w));
            }
        }
        #pragma unroll
        for (int g = 0; g < 8; g++) {
            float lo, hi; up2(acc[g], lo, hi);
            Os[p*260 + (2*oo)*8 + g]     = lo;   // [sp][c*8+g], c = o
            Os[p*260 + (2*oo + 1)*8 + g] = hi;
        }
    }
    __syncthreads();

    #pragma unroll
    for (int u = 0; u < 4; u++) {
        int e = t + 256*u;              // p'*64 + c4
        int pp = e >> 6, c4 = e & 63;
        int sp = pt*16 + pp;
        if (sp < NPP) {
            float4 v = *(const float4*)(Os + pp*260 + c4*4);
            *(float4*)(gout + (long)(b*NPP + sp)*256 + c4*4) = v;
        }
    }
}

// ================= attention (exact R11 version) =================
__device__ __forceinline__ void sgemm_pass(float* Ks, const float* qs,
                                           int r0, int cb, int lcb,
                                           bool valid, bool active, float* rsum) {
    u64 acc[8][2];
    #pragma unroll
    for (int i = 0; i < 8; i++) { acc[i][0] = 0ull; acc[i][1] = 0ull; }
    #pragma unroll 4
    for (int cc = 0; cc < 32; cc++) {
        ulonglong2 k = *(const ulonglong2*)(Ks + cc*MSK + lcb);
        float4 qa = *(const float4*)(qs + cc*32 + r0);
        float4 qb = *(const float4*)(qs + cc*32 + r0 + 4);
        float qv[8] = {qa.x, qa.y, qa.z, qa.w, qb.x, qb.y, qb.z, qb.w};
        #pragma unroll
        for (int i = 0; i < 8; i++) {
            u64 q2 = pk2(qv[i], qv[i]);
            FMA2(acc[i][0], q2, k.x);
            FMA2(acc[i][1], q2, k.y);
        }
    }
    #pragma unroll
    for (int i = 0; i < 8; i++) {
        float l0, h0, l1, h1;
        up2(acc[i][0], l0, h0); up2(acc[i][1], l1, h1);
        float e0 = ex2(l0), e1 = ex2(h0), e2 = ex2(l1), e3 = ex2(h1);
        if (valid) rsum[i] += e0 + e1 + e2 + e3;
        if (active) {
            u64 s0 = valid ? pk2(e0, e1) : 0ull;
            u64 s1 = valid ? pk2(e2, e3) : 0ull;
            *(ulonglong2*)(Ks + (r0 + i)*MSK + cb) = make_ulonglong2(s0, s1);
        }
    }
}

// 7 warps x 64 cols, 2 passes of 32 cols
__device__ __forceinline__ void sgemm_warp(float* Ks, const float* qs, float* mb,
                                           int w, int tx) {
    int r0 = (tx >> 3) * 8;
    int c0 = w*64 + (tx & 7)*4;      // pass 0 cols
    int c1 = c0 + 32;                // pass 1 cols
    bool a1 = (c1 < VPAD);
    int lc1 = a1 ? c1 : 0;
    float rsum[8];
    #pragma unroll
    for (int i = 0; i < 8; i++) rsum[i] = 0.f;
    sgemm_pass(Ks, qs, r0, c0, c0, c0 < NM, true, rsum);
    sgemm_pass(Ks, qs, r0, c1, lc1, c1 < NM, a1, rsum);
    #pragma unroll
    for (int i = 0; i < 8; i++) {
        float s = rsum[i];
        s += __shfl_xor_sync(0xffffffffu, s, 1);
        s += __shfl_xor_sync(0xffffffffu, s, 2);
        s += __shfl_xor_sync(0xffffffffu, s, 4);
        if ((tx & 7) == 0) mb[w*32 + r0 + i] = s;
    }
}

__global__ void __launch_bounds__(256, 3) attn_kernel(const float* __restrict__ rel_h,
                                                      const float* __restrict__ rel_w,
                                                      const float* __restrict__ gv,
                                                      float* __restrict__ out) {
    extern __shared__ float sm[];
    float* Ks   = sm + SM_KS;    // [32 c][MSK] -> E in place
    float* Agt  = sm + SM_AGT;   // [ij][g][g'] 49x8x8
    float* qs   = sm + SM_QS;    // [c][32 r]
    float* mb   = sm + SM_MB;    // [8 w][32 r]
    float* rinv = sm + SM_RI;
    float* Rs   = Ks;            // O-GEMM partials reuse Ks

    int bp = blockIdx.x;
    int b = bp >> 10, p = bp & 1023;
    int px = p >> 5, py = p & 31;
    int t = threadIdx.x;
    int tx = t & 31, ty = t >> 5;

    // stage q: qs[c*32 + hh*8 + g]
    {
        float4 qv = ((const float4*)(g_q + (long)bp*1024))[t];
        int s = t*4;
        int g = s >> 7, hh = (s >> 5) & 3, c0 = s & 31;
        qs[(c0+0)*32 + hh*8 + g] = qv.x;
        qs[(c0+1)*32 + hh*8 + g] = qv.y;
        qs[(c0+2)*32 + hh*8 + g] = qv.z;
        qs[(c0+3)*32 + hh*8 + g] = qv.w;
    }

    // stage K(+rel) [c][m]; STS conflict-free (MSK%32==8)
    {
        int c = t >> 3, gq = t & 7;
        float rh[KS];
        #pragma unroll
        for (int u = 0; u < KS; u++)
            rh[u] = (c < 16) ? rel_h[c*56 + gq*7 + u] : rel_w[(c - 16)*56 + gq*7 + u];
        const float* kbase = g_k + ((long)(b*HP + px)*HP + py)*256 + t;
        for (int i = 0; i < KS; i++) {
            #pragma unroll
            for (int j = 0; j < KS; j++) {
                int m = gq*49 + i*7 + j;
                int off = (i*HP + j)*256;
                float rel = (c < 16) ? rh[i] : rh[j];
                Ks[c*MSK + m] = kbase[off] + rel;
            }
        }
    }
    __syncthreads();

    // S = q^T K with fused exp + row sums (7 warps, 2 passes)
    if (ty < 7) sgemm_warp(Ks, qs, mb, ty, tx);
    __syncthreads();

    if (t < 32) {
        float s = 0.f;
        #pragma unroll
        for (int w = 0; w < 7; w++) s += mb[w*32 + t];
        rinv[t] = 1.f / s;
    }
    __syncthreads();

    // collapse heads into Agt[ij*64 + g*8 + g'] (reads only m < 392)
    for (int idx = t; idx < 3136; idx += 256) {
        int ij = idx >> 6;
        int rem = idx & 63;
        int g = rem >> 3, gp = rem & 7;
        int m = gp*49 + ij;
        float s = Ks[g*MSK + m]        * rinv[g]
                + Ks[(8+g)*MSK + m]    * rinv[8+g]
                + Ks[(16+g)*MSK + m]   * rinv[16+g]
                + Ks[(24+g)*MSK + m]   * rinv[24+g];
        Agt[idx] = s;
    }
    __syncthreads();

    // O-GEMM: V straight from gmem (coalesced, consumed once)
    {
        u64 og[8];
        #pragma unroll
        for (int g = 0; g < 8; g++) og[g] = 0ull;
        int c = tx, w = ty;
        const float* vb = gv + ((long)(b*HP + px)*HP + py)*256 + c*8;
        #pragma unroll
        for (int k = 0; k < 7; k++) {
            int ij = k*8 + w;
            if (ij < 49) {
                int i = ij / 7, j = ij - i*7;
                const float4* vp = (const float4*)(vb + (i*HP + j)*256);
                float4 va = vp[0], vbq = vp[1];
                u64 v0 = pk2(va.x, va.y), v1 = pk2(va.z, va.w);
                u64 v2 = pk2(vbq.x, vbq.y), v3 = pk2(vbq.z, vbq.w);
                const float* ab = Agt + ij*64;
                #pragma unroll
                for (int g = 0; g < 8; g++) {
                    ulonglong2 a0 = *(const ulonglong2*)(ab + g*8);
                    ulonglong2 a1 = *(const ulonglong2*)(ab + g*8 + 4);
                    FMA2(og[g], a0.x, v0);
                    FMA2(og[g], a0.y, v1);
                    FMA2(og[g], a1.x, v2);
                    FMA2(og[g], a1.y, v3);
                }
            }
        }
        __syncthreads();   // Agt/E reads done before Rs overwrites Ks
        #pragma unroll
        for (int g = 0; g < 8; g++) {
            float lo, hi; up2(og[g], lo, hi);
            Rs[w*264 + g*33 + c] = lo + hi;
        }
    }
    __syncthreads();

    // final reduce over 8 warps + scrambled store: out[b, g*32+px, py, c]
    {
        int c = tx, g = ty;
        float s = 0.f;
        #pragma unroll
        for (int w = 0; w < 8; w++) s += Rs[w*264 + g*33 + c];
        out[b*262144 + (g*32 + px)*1024 + py*32 + c] = s;
    }
}

// ---------------- launch ----------------
extern "C" void kernel_launch(void* const* d_in, const int* in_sizes, int n_in,
                              void* d_out, int out_size) {
    const float* x   = (const float*)d_in[0];
    const float* wq  = (const float*)d_in[1];
    const float* bq  = (const float*)d_in[2];
    const float* wk  = (const float*)d_in[3];
    const float* bk  = (const float*)d_in[4];
    const float* wv  = (const float*)d_in[5];
    const float* bv  = (const float*)d_in[6];
    const float* rlh = (const float*)d_in[7];
    const float* rlw = (const float*)d_in[8];
    float* out = (float*)d_out;

    cudaFuncSetAttribute(qconv_kernel, cudaFuncAttributeMaxDynamicSharedMemorySize, CONV_SMEM);
    cudaFuncSetAttribute(kvconv_kernel, cudaFuncAttributeMaxDynamicSharedMemorySize, KV_SMEM);
    cudaFuncSetAttribute(attn_kernel, cudaFuncAttributeMaxDynamicSharedMemorySize, ATTN_SMEM);

    qconv_kernel<<<dim3(16, 8, 4), 256, CONV_SMEM>>>(x, wq, bq);
    kvconv_kernel<<<dim3(91, 2, 4), 256, KV_SMEM>>>(x, wk, bk, wv, bv);

    float* gv_ptr = nullptr;
    cudaGetSymbolAddress((void**)&gv_ptr, g_v);
    attn_kernel<<<NB*NPIX, 256, ATTN_SMEM>>>(rlh, rlw, gv_ptr, out);
}

// round 16
// speedup vs baseline: 1.1246x; 1.0142x over previous
#include <cuda_runtime.h>

#define NB 4
#define NG 8
#define HH 32
#define WW 32
#define KS 7
#define PD 3
#define HP 38
#define NPP 1444      // HP*HP
#define NM 392
#define VPAD 416      // padded S cols (stored zeros; collapse reads only m<392)
#define MSK 424       // mod32=8: K-staging STS conflict-free; mult of 4
#define NPIX 1024

#define SM_KS  0
#define SM_AGT (32*MSK)            // 13568 ; Agt[ij*64 + g*8 + g'] (3136)
#define SM_QS  (SM_AGT + 3136)     // 16704 ; [32 c][32 r]
#define SM_MB  (SM_QS + 1024)      // 17728  [8w][32r]
#define SM_RI  (SM_MB + 256)       // 17984
#define ATTN_SMEM ((SM_RI + 32)*4) // 72064 B -> 3 CTA/SM

// fused conv smem — qconv view
#define QC_WS 0                    // [128 o][33]
#define QC_XS (128*33)             // [32 k][64 p]
#define QC_OS (QC_XS + 32*64)      // [64 p][132]
// kv view
#define KV_WS 0                    // [8 g][32 o][36]
#define KV_XS (8*32*36)            // 9216 ; [8 g][16 p][36]
#define KV_OS (KV_XS + 8*16*36)    // 13824 ; [16 p][260]
#define CONV_SMEM ((KV_OS + 16*260)*4)   // 71936 B (kv view is larger)

__device__ float g_q[NB*NPIX*1024];   // [b][p][g*128 + hh*32 + c]  (q * log2e)
__device__ float g_k[NB*NPP*256];     // [b][sp][c*8+g]
__device__ float g_v[NB*NPP*256];

typedef unsigned long long u64;
__device__ __forceinline__ u64 pk2(float a, float b) {
    u64 r; asm("mov.b64 %0, {%1,%2};" : "=l"(r) : "f"(a), "f"(b)); return r;
}
__device__ __forceinline__ void up2(u64 v, float& a, float& b) {
    asm("mov.b64 {%0,%1}, %2;" : "=f"(a), "=f"(b) : "l"(v));
}
#define FMA2(d,a,b) asm("fma.rn.f32x2 %0, %1, %2, %0;" : "+l"(d) : "l"(a), "l"(b))
__device__ __forceinline__ float ex2(float x) {
    float r; asm("ex2.approx.f32 %0, %1;" : "=f"(r) : "f"(x)); return r;
}

// ============ fused conv: CTAs 0..511 qconv, 512..1239 kvconv ============
__global__ void __launch_bounds__(256) conv_kernel(const float* __restrict__ x,
                                                   const float* __restrict__ wq,
                                                   const float* __restrict__ bq,
                                                   const float* __restrict__ wk,
                                                   const float* __restrict__ bk,
                                                   const float* __restrict__ wv,
                                                   const float* __restrict__ bv) {
    extern __shared__ float sm[];
    int cid = blockIdx.x;
    int t = threadIdx.x;

    if (cid < 512) {
        // ---- qconv: per (b,g) GEMM 128o x 64p, K=32; q scaled by log2e ----
        int pt = cid & 15, g = (cid >> 4) & 7, b = cid >> 7;
        float* Ws = sm + QC_WS;
        float* Xs = sm + QC_XS;
        float* Os = sm + QC_OS;
        #pragma unroll
        for (int u = 0; u < 16; u++) {
            int e = t + 256*u;
            Ws[(e >> 5)*33 + (e & 31)] = wq[g*4096 + e];
        }
        #pragma unroll
        for (int u = 0; u < 8; u++) {
            int e = t + 256*u;
            int k = e >> 6, p = e & 63;
            Xs[e] = x[((b*NG + g)*32 + k)*1024 + pt*64 + p];
        }
        __syncthreads();

        int to = t >> 4, tp = t & 15;
        int o0 = to*8, p0 = tp*4;
        u64 a[8][2];
        #pragma unroll
        for (int i = 0; i < 8; i++) {
            float bi = bq[g*128 + o0 + i];
            a[i][0] = pk2(bi, bi); a[i][1] = a[i][0];
        }
        #pragma unroll 4
        for (int k = 0; k < 32; k++) {
            ulonglong2 xv = *(const ulonglong2*)(Xs + k*64 + p0);
            #pragma unroll
            for (int i = 0; i < 8; i++) {
                float w = Ws[(o0 + i)*33 + k];
                u64 w2 = pk2(w, w);
                FMA2(a[i][0], w2, xv.x);
                FMA2(a[i][1], w2, xv.y);
            }
        }
        const float L2E = 1.4426950408889634f;
        #pragma unroll
        for (int i = 0; i < 8; i++)
            #pragma unroll
            for (int j = 0; j < 2; j++) {
                float lo, hi; up2(a[i][j], lo, hi);
                Os[(p0 + 2*j    )*132 + o0 + i] = lo * L2E;
                Os[(p0 + 2*j + 1)*132 + o0 + i] = hi * L2E;
            }
        __syncthreads();
        #pragma unroll
        for (int u = 0; u < 8; u++) {
            int e = t + 256*u;
            int p = e >> 5, o4 = e & 31;
            float4 v = *(const float4*)(Os + p*132 + o4*4);
            *(float4*)(g_q + (long)(b*1024 + pt*64 + p)*1024 + g*128 + o4*4) = v;
        }
    } else {
        // ---- kv conv: all 8 groups, 16 padded px/CTA, coalesced output ----
        int e0 = cid - 512;            // 0..727
        int pt = e0 % 91;
        int r  = e0 / 91;              // 0..7
        int kvsel = r & 1, b = r >> 1;
        float* Ws = sm + KV_WS;   // [g*1152 + o*36 + k]
        float* Xs = sm + KV_XS;   // [g*576 + p*36 + k]
        float* Os = sm + KV_OS;   // [p*260 + c8]
        __shared__ float bs[256];
        const float* w  = kvsel ? wv : wk;
        const float* bb = kvsel ? bv : bk;
        float* gout = kvsel ? g_v : g_k;

        #pragma unroll
        for (int u = 0; u < 32; u++) {
            int e = t + 256*u;              // g*1024 + o*32 + k
            int g = e >> 10, o = (e >> 5) & 31, k = e & 31;
            Ws[g*1152 + o*36 + k] = w[e];
        }
        bs[t] = bb[t];
        #pragma unroll
        for (int u = 0; u < 16; u++) {
            int e = t + 256*u;              // g*512 + k*16 + p
            int g = e >> 9, k = (e >> 4) & 31, p = e & 15;
            int sp = pt*16 + p;
            float v = 0.f;
            if (sp < NPP) {
                int sy = sp / HP, sx = sp - sy*HP;
                int iy = sy - PD, ix = sx - PD;
                if (iy >= 0 && iy < HH && ix >= 0 && ix < WW)
                    v = x[((b*NG + g)*32 + k)*1024 + iy*32 + ix];
            }
            Xs[g*576 + p*36 + k] = v;
        }
        __syncthreads();

        {
            int p = t & 15, oo = t >> 4;
            u64 acc[8];
            #pragma unroll
            for (int g = 0; g < 8; g++)
                acc[g] = pk2(bs[g*32 + 2*oo], bs[g*32 + 2*oo + 1]);
            #pragma unroll
            for (int g = 0; g < 8; g++) {
                const float* xr = Xs + g*576 + p*36;
                const float* w0 = Ws + g*1152 + (2*oo)*36;
                const float* w1 = w0 + 36;
                #pragma unroll
                for (int k4 = 0; k4 < 8; k4++) {
                    float4 xv = *(const float4*)(xr + k4*4);
                    float4 wa = *(const float4*)(w0 + k4*4);
                    float4 wb = *(const float4*)(w1 + k4*4);
                    FMA2(acc[g], pk2(xv.x, xv.x), pk2(wa.x, wb.x));
                    FMA2(acc[g], pk2(xv.y, xv.y), pk2(wa.y, wb.y));
                    FMA2(acc[g], pk2(xv.z, xv.z), pk2(wa.z, wb.z));
                    FMA2(acc[g], pk2(xv.w, xv.w), pk2(wa.w, wb.w));
                }
            }
            #pragma unroll
            for (int g = 0; g < 8; g++) {
                float lo, hi; up2(acc[g], lo, hi);
                Os[p*260 + (2*oo)*8 + g]     = lo;   // [sp][c*8+g], c = o
                Os[p*260 + (2*oo + 1)*8 + g] = hi;
            }
        }
        __syncthreads();

        #pragma unroll
        for (int u = 0; u < 4; u++) {
            int e = t + 256*u;              // p'*64 + c4
            int pp = e >> 6, c4 = e & 63;
            int sp = pt*16 + pp;
            if (sp < NPP) {
                float4 v = *(const float4*)(Os + pp*260 + c4*4);
                *(float4*)(gout + (long)(b*NPP + sp)*256 + c4*4) = v;
            }
        }
    }
}

// ================= attention (exact R11 version) =================
__device__ __forceinline__ void sgemm_pass(float* Ks, const float* qs,
                                           int r0, int cb, int lcb,
                                           bool valid, bool active, float* rsum) {
    u64 acc[8][2];
    #pragma unroll
    for (int i = 0; i < 8; i++) { acc[i][0] = 0ull; acc[i][1] = 0ull; }
    #pragma unroll 4
    for (int cc = 0; cc < 32; cc++) {
        ulonglong2 k = *(const ulonglong2*)(Ks + cc*MSK + lcb);
        float4 qa = *(const float4*)(qs + cc*32 + r0);
        float4 qb = *(const float4*)(qs + cc*32 + r0 + 4);
        float qv[8] = {qa.x, qa.y, qa.z, qa.w, qb.x, qb.y, qb.z, qb.w};
        #pragma unroll
        for (int i = 0; i < 8; i++) {
            u64 q2 = pk2(qv[i], qv[i]);
            FMA2(acc[i][0], q2, k.x);
            FMA2(acc[i][1], q2, k.y);
        }
    }
    #pragma unroll
    for (int i = 0; i < 8; i++) {
        float l0, h0, l1, h1;
        up2(acc[i][0], l0, h0); up2(acc[i][1], l1, h1);
        float e0 = ex2(l0), e1 = ex2(h0), e2 = ex2(l1), e3 = ex2(h1);
        if (valid) rsum[i] += e0 + e1 + e2 + e3;
        if (active) {
            u64 s0 = valid ? pk2(e0, e1) : 0ull;
            u64 s1 = valid ? pk2(e2, e3) : 0ull;
            *(ulonglong2*)(Ks + (r0 + i)*MSK + cb) = make_ulonglong2(s0, s1);
        }
    }
}

// 7 warps x 64 cols, 2 passes of 32 cols
__device__ __forceinline__ void sgemm_warp(float* Ks, const float* qs, float* mb,
                                           int w, int tx) {
    int r0 = (tx >> 3) * 8;
    int c0 = w*64 + (tx & 7)*4;      // pass 0 cols
    int c1 = c0 + 32;                // pass 1 cols
    bool a1 = (c1 < VPAD);
    int lc1 = a1 ? c1 : 0;
    float rsum[8];
    #pragma unroll
    for (int i = 0; i < 8; i++) rsum[i] = 0.f;
    sgemm_pass(Ks, qs, r0, c0, c0, c0 < NM, true, rsum);
    sgemm_pass(Ks, qs, r0, c1, lc1, c1 < NM, a1, rsum);
    #pragma unroll
    for (int i = 0; i < 8; i++) {
        float s = rsum[i];
        s += __shfl_xor_sync(0xffffffffu, s, 1);
        s += __shfl_xor_sync(0xffffffffu, s, 2);
        s += __shfl_xor_sync(0xffffffffu, s, 4);
        if ((tx & 7) == 0) mb[w*32 + r0 + i] = s;
    }
}

__global__ void __launch_bounds__(256, 3) attn_kernel(const float* __restrict__ rel_h,
                                                      const float* __restrict__ rel_w,
                                                      const float* __restrict__ gv,
                                                      float* __restrict__ out) {
    extern __shared__ float sm[];
    float* Ks   = sm + SM_KS;    // [32 c][MSK] -> E in place
    float* Agt  = sm + SM_AGT;   // [ij][g][g'] 49x8x8
    float* qs   = sm + SM_QS;    // [c][32 r]
    float* mb   = sm + SM_MB;    // [8 w][32 r]
    float* rinv = sm + SM_RI;
    float* Rs   = Ks;            // O-GEMM partials reuse Ks

    int bp = blockIdx.x;
    int b = bp >> 10, p = bp & 1023;
    int px = p >> 5, py = p & 31;
    int t = threadIdx.x;
    int tx = t & 31, ty = t >> 5;

    // stage q: qs[c*32 + hh*8 + g]
    {
        float4 qv = ((const float4*)(g_q + (long)bp*1024))[t];
        int s = t*4;
        int g = s >> 7, hh = (s >> 5) & 3, c0 = s & 31;
        qs[(c0+0)*32 + hh*8 + g] = qv.x;
        qs[(c0+1)*32 + hh*8 + g] = qv.y;
        qs[(c0+2)*32 + hh*8 + g] = qv.z;
        qs[(c0+3)*32 + hh*8 + g] = qv.w;
    }

    // stage K(+rel) [c][m]; STS conflict-free (MSK%32==8)
    {
        int c = t >> 3, gq = t & 7;
        float rh[KS];
        #pragma unroll
        for (int u = 0; u < KS; u++)
            rh[u] = (c < 16) ? rel_h[c*56 + gq*7 + u] : rel_w[(c - 16)*56 + gq*7 + u];
        const float* kbase = g_k + ((long)(b*HP + px)*HP + py)*256 + t;
        for (int i = 0; i < KS; i++) {
            #pragma unroll
            for (int j = 0; j < KS; j++) {
                int m = gq*49 + i*7 + j;
                int off = (i*HP + j)*256;
                float rel = (c < 16) ? rh[i] : rh[j];
                Ks[c*MSK + m] = kbase[off] + rel;
            }
        }
    }
    __syncthreads();

    // S = q^T K with fused exp + row sums (7 warps, 2 passes)
    if (ty < 7) sgemm_warp(Ks, qs, mb, ty, tx);
    __syncthreads();

    if (t < 32) {
        float s = 0.f;
        #pragma unroll
        for (int w = 0; w < 7; w++) s += mb[w*32 + t];
        rinv[t] = 1.f / s;
    }
    __syncthreads();

    // collapse heads into Agt[ij*64 + g*8 + g'] (reads only m < 392)
    for (int idx = t; idx < 3136; idx += 256) {
        int ij = idx >> 6;
        int rem = idx & 63;
        int g = rem >> 3, gp = rem & 7;
        int m = gp*49 + ij;
        float s = Ks[g*MSK + m]        * rinv[g]
                + Ks[(8+g)*MSK + m]    * rinv[8+g]
                + Ks[(16+g)*MSK + m]   * rinv[16+g]
                + Ks[(24+g)*MSK + m]   * rinv[24+g];
        Agt[idx] = s;
    }
    __syncthreads();

    // O-GEMM: V straight from gmem (coalesced, consumed once)
    {
        u64 og[8];
        #pragma unroll
        for (int g = 0; g < 8; g++) og[g] = 0ull;
        int c = tx, w = ty;
        const float* vb = gv + ((long)(b*HP + px)*HP + py)*256 + c*8;
        #pragma unroll
        for (int k = 0; k < 7; k++) {
            int ij = k*8 + w;
            if (ij < 49) {
                int i = ij / 7, j = ij - i*7;
                const float4* vp = (const float4*)(vb + (i*HP + j)*256);
                float4 va = vp[0], vbq = vp[1];
                u64 v0 = pk2(va.x, va.y), v1 = pk2(va.z, va.w);
                u64 v2 = pk2(vbq.x, vbq.y), v3 = pk2(vbq.z, vbq.w);
                const float* ab = Agt + ij*64;
                #pragma unroll
                for (int g = 0; g < 8; g++) {
                    ulonglong2 a0 = *(const ulonglong2*)(ab + g*8);
                    ulonglong2 a1 = *(const ulonglong2*)(ab + g*8 + 4);
                    FMA2(og[g], a0.x, v0);
                    FMA2(og[g], a0.y, v1);
                    FMA2(og[g], a1.x, v2);
                    FMA2(og[g], a1.y, v3);
                }
            }
        }
        __syncthreads();   // Agt/E reads done before Rs overwrites Ks
        #pragma unroll
        for (int g = 0; g < 8; g++) {
            float lo, hi; up2(og[g], lo, hi);
            Rs[w*264 + g*33 + c] = lo + hi;
        }
    }
    __syncthreads();

    // final reduce over 8 warps + scrambled store: out[b, g*32+px, py, c]
    {
        int c = tx, g = ty;
        float s = 0.f;
        #pragma unroll
        for (int w = 0; w < 8; w++) s += Rs[w*264 + g*33 + c];
        out[b*262144 + (g*32 + px)*1024 + py*32 + c] = s;
    }
}

// ---------------- launch ----------------
extern "C" void kernel_launch(void* const* d_in, const int* in_sizes, int n_in,
                              void* d_out, int out_size) {
    const float* x   = (const float*)d_in[0];
    const float* wq  = (const float*)d_in[1];
    const float* bq  = (const float*)d_in[2];
    const float* wk  = (const float*)d_in[3];
    const float* bk  = (const float*)d_in[4];
    const float* wv  = (const float*)d_in[5];
    const float* bv  = (const float*)d_in[6];
    const float* rlh = (const float*)d_in[7];
    const float* rlw = (const float*)d_in[8];
    float* out = (float*)d_out;

    cudaFuncSetAttribute(conv_kernel, cudaFuncAttributeMaxDynamicSharedMemorySize, CONV_SMEM);
    cudaFuncSetAttribute(attn_kernel, cudaFuncAttributeMaxDynamicSharedMemorySize, ATTN_SMEM);

    conv_kernel<<<1240, 256, CONV_SMEM>>>(x, wq, bq, wk, bk, wv, bv);

    float* gv_ptr = nullptr;
    cudaGetSymbolAddress((void**)&gv_ptr, g_v);
    attn_kernel<<<NB*NPIX, 256, ATTN_SMEM>>>(rlh, rlw, gv_ptr, out);
}